// round 1
// baseline (speedup 1.0000x reference)
#include <cuda_runtime.h>

#define NEARZERO_F 1e-5f
#define WARM_UP    365
#define LENF       15
#define N_PHY      12
#define NMUL       4

// PHY_LB / (PHY_UB - PHY_LB) baked in:
// beta[1,6] fc[50,1000] k0[.05,.9] k1[.01,.5] k2[.001,.2] lp[.2,1]
// perc[0,10] uzl[0,100] tt[-2.5,2.5] cfmax[.5,10] cfr[0,.1] cwh[0,.2]

__global__ __launch_bounds__(128)
void hbv_fused_kernel(const float* __restrict__ x,    // [T, G, 3]
                      const float* __restrict__ par,  // [1, G, 50]
                      float* __restrict__ out,        // [T-365, G, 1]
                      int T, int G) {
    int tid = blockIdx.x * 128 + threadIdx.x;
    if (tid >= G * NMUL) return;
    int g = tid >> 2;       // gauge
    int m = tid & 3;        // multiplier; lanes 4g..4g+3 share a gauge

    // ---- physical parameters for this (g, m) ----
    const float* pg = par + g * (N_PHY * NMUL + 2);
    float raw[N_PHY];
#pragma unroll
    for (int i = 0; i < N_PHY; i++) raw[i] = pg[i * NMUL + m];

    const float beta  = 1.0f   + raw[0]  * 5.0f;
    const float fc    = 50.0f  + raw[1]  * 950.0f;
    const float k0    = 0.05f  + raw[2]  * 0.85f;
    const float k1    = 0.01f  + raw[3]  * 0.49f;
    const float k2    = 0.001f + raw[4]  * 0.199f;
    const float lp    = 0.2f   + raw[5]  * 0.8f;
    const float perc  =          raw[6]  * 10.0f;
    const float uzl   =          raw[7]  * 100.0f;
    const float tt    = -2.5f  + raw[8]  * 5.0f;
    const float cfmax = 0.5f   + raw[9]  * 9.5f;
    const float cfr   =          raw[10] * 0.1f;
    const float cwh   =          raw[11] * 0.2f;

    const float inv_fc    = 1.0f / fc;
    const float cfrmax    = cfr * cfmax;
    const float inv_lpfc  = 1.0f / (lp * fc);

    // ---- routing weights (gamma kernel); Gamma(aa)*th^aa cancels in normalization ----
    const float a  = pg[N_PHY * NMUL + 0] * 2.9f;
    const float b  = pg[N_PHY * NMUL + 1] * 6.5f;
    const float aa = fmaxf(a, 0.0f) + 0.1f;
    const float th = fmaxf(b, 0.0f) + 0.5f;
    float w[LENF];
    float wsum = 0.0f;
#pragma unroll
    for (int k = 0; k < LENF; k++) {
        float tg = (float)k + 0.5f;
        float u  = powf(tg, aa - 1.0f) * expf(-tg / th);
        w[k] = u;
        wsum += u;
    }
    const float winv = 1.0f / wsum;
#pragma unroll
    for (int k = 0; k < LENF; k++) w[k] *= winv;

    // ---- states ----
    float sp  = 0.001f;   // snowpack
    float mw  = 0.001f;   // meltwater
    float sm  = 0.001f;   // soil moisture
    float suz = 0.001f;   // upper zone
    float slz = 0.001f;   // lower zone

    // ---- transposed-form FIR shift registers ----
    float s0=0.f,s1=0.f,s2=0.f,s3=0.f,s4=0.f,s5=0.f,s6=0.f,
          s7=0.f,s8=0.f,s9=0.f,s10=0.f,s11=0.f,s12=0.f,s13=0.f;

    // ---- input prefetch ring, depth 8 ----
    const float* xg = x + g * 3;
    const int stride = G * 3;
    float bx[8], by[8], bz[8];
#pragma unroll
    for (int k = 0; k < 8; k++) {
        const float* p = xg + k * stride;
        bx[k] = __ldg(p + 0);
        by[k] = __ldg(p + 1);
        bz[k] = __ldg(p + 2);
    }

    for (int t0 = 0; t0 < T; t0 += 8) {
#pragma unroll
        for (int k = 0; k < 8; k++) {
            const int t = t0 + k;
            const float P  = bx[k];
            const float Tt = by[k];
            const float PE = bz[k];

            // prefetch t+8 (issues early; covered by ~8 steps of chain latency)
            const int tn = t + 8;
            if (tn < T) {
                const float* p = xg + tn * stride;
                bx[k] = __ldg(p + 0);
                by[k] = __ldg(p + 1);
                bz[k] = __ldg(p + 2);
            }

            // ---- input-only terms (off the state chain) ----
            const float rain  = (Tt >= tt) ? P : 0.0f;
            const float snow  = P - rain;
            const float meltA = fmaxf(cfmax * (Tt - tt), 0.0f);
            const float refA  = fmaxf(cfrmax * (tt - Tt), 0.0f);
            const float cpe   = PE * inv_lpfc;          // evap slope
            const float omc   = 1.0f - cpe;

            // ---- snow / meltwater ----
            sp += snow;
            const float melt = fminf(meltA, sp);
            sp -= melt;
            mw += melt;
            const float refreeze = fminf(refA, mw);
            sp += refreeze;
            mw -= refreeze;
            const float tosoil = fmaxf(mw - cwh * sp, 0.0f);
            mw -= tosoil;

            // ---- soil moisture ----
            float sw = __powf(sm * inv_fc, beta);        // (sm/fc)^beta
            sw = fminf(sw, 1.0f);                        // clip upper (lower is free)
            const float rt       = rain + tosoil;
            const float recharge = rt * sw;
            const float sm2      = fmaf(-rt, sw, sm + rt);   // sm + rt - rt*sw
            const float excess   = fmaxf(sm2 - fc, 0.0f);
            const float sm3      = fminf(sm2, fc);           // sm2 - excess
            // etact = min(sm3, PE*clip(sm3/(lp*fc),0,1)); sm = max(sm3-etact, NEARZERO)
            sm = fmaxf(fmaxf(sm3 - PE, sm3 * omc), NEARZERO_F);

            // ---- upper / lower zone ----
            suz += recharge + excess;
            const float prc = fminf(suz, perc);
            suz -= prc;
            const float q0v = k0 * fmaxf(suz - uzl, 0.0f);
            suz -= q0v;
            const float q1v = k1 * suz;
            suz -= q1v;
            slz += prc;
            const float q2v = k2 * slz;
            slz -= q2v;

            // ---- mean over 4 multipliers (lanes 4g..4g+3) ----
            float q = q0v + q1v + q2v;
            q += __shfl_xor_sync(0xffffffffu, q, 1);
            q += __shfl_xor_sync(0xffffffffu, q, 2);
            q *= 0.25f;

            // ---- transposed-form 15-tap FIR (does not feed back into states) ----
            const float y = fmaf(w[0], q, s0);
            s0  = fmaf(w[1],  q, s1);
            s1  = fmaf(w[2],  q, s2);
            s2  = fmaf(w[3],  q, s3);
            s3  = fmaf(w[4],  q, s4);
            s4  = fmaf(w[5],  q, s5);
            s5  = fmaf(w[6],  q, s6);
            s6  = fmaf(w[7],  q, s7);
            s7  = fmaf(w[8],  q, s8);
            s8  = fmaf(w[9],  q, s9);
            s9  = fmaf(w[10], q, s10);
            s10 = fmaf(w[11], q, s11);
            s11 = fmaf(w[12], q, s12);
            s12 = fmaf(w[13], q, s13);
            s13 = w[14] * q;

            if (t >= WARM_UP && m == 0) {
                out[(t - WARM_UP) * G + g] = y;
            }
        }
    }
}

extern "C" void kernel_launch(void* const* d_in, const int* in_sizes, int n_in,
                              void* d_out, int out_size) {
    const float* x   = (const float*)d_in[0];   // [T, G, 3]
    const float* par = (const float*)d_in[1];   // [1, G, 50]
    float* out = (float*)d_out;                 // [T-365, G, 1]

    const int G = in_sizes[1] / (N_PHY * NMUL + 2);
    const int T = in_sizes[0] / (3 * G);

    const int threads = G * NMUL;
    const int block = 128;
    const int grid = (threads + block - 1) / block;
    hbv_fused_kernel<<<grid, block>>>(x, par, out, T, G);
}